// round 1
// baseline (speedup 1.0000x reference)
#include <cuda_runtime.h>
#include <mma.h>

using namespace nvcuda;

#define BB 4
#define LL 2048
#define DD 1024
#define HH 16
#define DKH 64

// ---------------- scratch (static device allocations) ----------------
__device__ float g_sem[(size_t)BB * LL * DD];
__device__ float g_qp [(size_t)BB * LL * DD];
__device__ float g_kp [(size_t)BB * LL * DD];
__device__ float g_vp [(size_t)BB * LL * DD];
__device__ float g_op [(size_t)BB * LL * DD];

// ---------------- tf32 GEMM: C[m,n] = sum_k X[m,k]*W[n,k] + bias[n] (+ addend[m,n]) ----------------
// X: [M, 1024] row-major, W: [1024, 1024] row-major (N x K), K = N = 1024.
#define GK 1024
#define GN 1024
#define GBM 128
#define GBN 64
#define GBK 32
#define XPAD 36
#define CPAD 68

__global__ __launch_bounds__(256) void gemm_tf32_kernel(
    const float* __restrict__ X, const float* __restrict__ W,
    const float* __restrict__ bias, const float* __restrict__ addend,
    float* __restrict__ C)
{
    __shared__ float smem[GBM * CPAD];           // 8704 floats, reused for epilogue
    float* Xs = smem;                            // [GBM][XPAD]
    float* Ws = smem + GBM * XPAD;               // [GBN][XPAD]

    const int tid = threadIdx.x;
    const int wid = tid >> 5;
    const int warp_m = wid & 3;                  // 4 row-groups of 32
    const int warp_n = wid >> 2;                 // 2 col-groups of 32
    const int m0 = blockIdx.y * GBM;
    const int n0 = blockIdx.x * GBN;

    wmma::fragment<wmma::accumulator, 16, 16, 8, float> c[2][2];
    #pragma unroll
    for (int i = 0; i < 2; i++)
        #pragma unroll
        for (int j = 0; j < 2; j++) wmma::fill_fragment(c[i][j], 0.0f);

    for (int k0 = 0; k0 < GK; k0 += GBK) {
        // stage X tile 128x32 (1024 float4)
        #pragma unroll
        for (int j = 0; j < 4; j++) {
            int idx = tid + 256 * j;
            int r = idx >> 3, c4 = idx & 7;
            float4 v = *(const float4*)(X + (size_t)(m0 + r) * GK + k0 + c4 * 4);
            *(float4*)(Xs + r * XPAD + c4 * 4) = v;
        }
        // stage W tile 64x32 (512 float4)
        #pragma unroll
        for (int j = 0; j < 2; j++) {
            int idx = tid + 256 * j;
            int r = idx >> 3, c4 = idx & 7;
            float4 v = *(const float4*)(W + (size_t)(n0 + r) * GK + k0 + c4 * 4);
            *(float4*)(Ws + r * XPAD + c4 * 4) = v;
        }
        __syncthreads();

        #pragma unroll
        for (int kk = 0; kk < GBK; kk += 8) {
            wmma::fragment<wmma::matrix_a, 16, 16, 8, wmma::precision::tf32, wmma::row_major> a[2];
            wmma::fragment<wmma::matrix_b, 16, 16, 8, wmma::precision::tf32, wmma::col_major> b[2];
            #pragma unroll
            for (int i = 0; i < 2; i++) {
                wmma::load_matrix_sync(a[i], Xs + (warp_m * 32 + i * 16) * XPAD + kk, XPAD);
                #pragma unroll
                for (int t = 0; t < a[i].num_elements; t++) a[i].x[t] = wmma::__float_to_tf32(a[i].x[t]);
            }
            #pragma unroll
            for (int j = 0; j < 2; j++) {
                wmma::load_matrix_sync(b[j], Ws + (warp_n * 32 + j * 16) * XPAD + kk, XPAD);
                #pragma unroll
                for (int t = 0; t < b[j].num_elements; t++) b[j].x[t] = wmma::__float_to_tf32(b[j].x[t]);
            }
            #pragma unroll
            for (int i = 0; i < 2; i++)
                #pragma unroll
                for (int j = 0; j < 2; j++) wmma::mma_sync(c[i][j], a[i], b[j], c[i][j]);
        }
        __syncthreads();
    }

    // epilogue through smem (bias + optional addend)
    float* Cs = smem;                            // [GBM][CPAD]
    #pragma unroll
    for (int i = 0; i < 2; i++)
        #pragma unroll
        for (int j = 0; j < 2; j++)
            wmma::store_matrix_sync(Cs + (warp_m * 32 + i * 16) * CPAD + warp_n * 32 + j * 16,
                                    c[i][j], CPAD, wmma::mem_row_major);
    __syncthreads();

    const int col = tid & 63;
    const int rb  = tid >> 6;
    const float bv = bias[n0 + col];
    if (addend) {
        #pragma unroll 8
        for (int i = 0; i < 32; i++) {
            int r = rb + i * 4;
            size_t gi = (size_t)(m0 + r) * GN + n0 + col;
            C[gi] = Cs[r * CPAD + col] + bv + addend[gi];
        }
    } else {
        #pragma unroll 8
        for (int i = 0; i < 32; i++) {
            int r = rb + i * 4;
            size_t gi = (size_t)(m0 + r) * GN + n0 + col;
            C[gi] = Cs[r * CPAD + col] + bv;
        }
    }
}

// ---------------- attention: per (b, h, q-tile of 64) ----------------
// pass1: rowsum of exp(masked S).  pass2: recompute S, write normalized attn, O += P*V.
#define KPAD 68
#define SPAD 72

__global__ __launch_bounds__(256) void attn_kernel(
    const float* __restrict__ gq, const float* __restrict__ gk, const float* __restrict__ gv,
    const int* __restrict__ mask, float* __restrict__ attn, float* __restrict__ go)
{
    __shared__ float KVs[64 * KPAD];
    __shared__ float Ss [64 * SPAD];
    __shared__ float rowsum[64];
    __shared__ float rinv[64];
    __shared__ int   ms[64];

    const int tid = threadIdx.x;
    const int wid = tid >> 5;
    const int warp_r = wid >> 1;       // 4 groups: 16 q-rows each
    const int warp_c = wid & 1;        // 2 groups: 32 cols each
    const int b = blockIdx.z, h = blockIdx.y;
    const int q0 = blockIdx.x * 64;

    const float* Qb = gq + ((size_t)(b * LL + q0)) * DD + h * DKH;
    const float* Kb = gk + ((size_t)(b * LL)) * DD + h * DKH;
    const float* Vb = gv + ((size_t)(b * LL)) * DD + h * DKH;

    // preload Q a-fragments (constant across all k-tiles)
    wmma::fragment<wmma::matrix_a, 16, 16, 8, wmma::precision::tf32, wmma::row_major> aq[8];
    #pragma unroll
    for (int ks = 0; ks < 8; ks++) {
        wmma::load_matrix_sync(aq[ks], Qb + (size_t)(warp_r * 16) * DD + ks * 8, DD);
        #pragma unroll
        for (int t = 0; t < aq[ks].num_elements; t++) aq[ks].x[t] = wmma::__float_to_tf32(aq[ks].x[t]);
    }

    if (tid < 64) rowsum[tid] = 0.0f;

    const int r  = tid >> 2;            // q-row handled in elementwise steps
    const int c0 = (tid & 3) * 4;       // float4 column base (interleaved -> coalesced)
    const int mbase = b * LL;

    // ---------------- pass 1: row sums ----------------
    for (int kt = 0; kt < 32; kt++) {
        #pragma unroll
        for (int j = 0; j < 4; j++) {
            int idx = tid + 256 * j;
            int rr = idx >> 4, c4 = idx & 15;
            *(float4*)(KVs + rr * KPAD + c4 * 4) =
                *(const float4*)(Kb + (size_t)(kt * 64 + rr) * DD + c4 * 4);
        }
        if (tid < 64) ms[tid] = mask[mbase + kt * 64 + tid];
        __syncthreads();

        wmma::fragment<wmma::accumulator, 16, 16, 8, float> cs[2];
        wmma::fill_fragment(cs[0], 0.0f);
        wmma::fill_fragment(cs[1], 0.0f);
        #pragma unroll
        for (int ks = 0; ks < 8; ks++) {
            wmma::fragment<wmma::matrix_b, 16, 16, 8, wmma::precision::tf32, wmma::col_major> bk[2];
            #pragma unroll
            for (int j = 0; j < 2; j++) {
                wmma::load_matrix_sync(bk[j], KVs + (warp_c * 32 + j * 16) * KPAD + ks * 8, KPAD);
                #pragma unroll
                for (int t = 0; t < bk[j].num_elements; t++) bk[j].x[t] = wmma::__float_to_tf32(bk[j].x[t]);
            }
            wmma::mma_sync(cs[0], aq[ks], bk[0], cs[0]);
            wmma::mma_sync(cs[1], aq[ks], bk[1], cs[1]);
        }
        wmma::store_matrix_sync(Ss + (warp_r * 16) * SPAD + warp_c * 32,      cs[0], SPAD, wmma::mem_row_major);
        wmma::store_matrix_sync(Ss + (warp_r * 16) * SPAD + warp_c * 32 + 16, cs[1], SPAD, wmma::mem_row_major);
        __syncthreads();

        float acc = 0.0f;
        #pragma unroll
        for (int i4 = 0; i4 < 4; i4++) {
            int c = c0 + i4 * 16;
            float4 s4 = *(const float4*)(Ss + r * SPAD + c);
            acc += ms[c + 0] ? __expf(s4.x * 0.125f) : 0.0f;
            acc += ms[c + 1] ? __expf(s4.y * 0.125f) : 0.0f;
            acc += ms[c + 2] ? __expf(s4.z * 0.125f) : 0.0f;
            acc += ms[c + 3] ? __expf(s4.w * 0.125f) : 0.0f;
        }
        acc += __shfl_xor_sync(0xffffffff, acc, 1);
        acc += __shfl_xor_sync(0xffffffff, acc, 2);
        if ((tid & 3) == 0) rowsum[r] += acc;
        __syncthreads();
    }
    if (tid < 64) rinv[tid] = 1.0f / rowsum[tid];
    __syncthreads();

    // ---------------- pass 2: write attn + O = P*V ----------------
    wmma::fragment<wmma::accumulator, 16, 16, 8, float> of[2];
    wmma::fill_fragment(of[0], 0.0f);
    wmma::fill_fragment(of[1], 0.0f);
    const size_t attn_base = ((size_t)(b * HH + h) * LL + q0) * LL;

    for (int kt = 0; kt < 32; kt++) {
        #pragma unroll
        for (int j = 0; j < 4; j++) {
            int idx = tid + 256 * j;
            int rr = idx >> 4, c4 = idx & 15;
            *(float4*)(KVs + rr * KPAD + c4 * 4) =
                *(const float4*)(Kb + (size_t)(kt * 64 + rr) * DD + c4 * 4);
        }
        if (tid < 64) ms[tid] = mask[mbase + kt * 64 + tid];
        __syncthreads();

        wmma::fragment<wmma::accumulator, 16, 16, 8, float> cs[2];
        wmma::fill_fragment(cs[0], 0.0f);
        wmma::fill_fragment(cs[1], 0.0f);
        #pragma unroll
        for (int ks = 0; ks < 8; ks++) {
            wmma::fragment<wmma::matrix_b, 16, 16, 8, wmma::precision::tf32, wmma::col_major> bk[2];
            #pragma unroll
            for (int j = 0; j < 2; j++) {
                wmma::load_matrix_sync(bk[j], KVs + (warp_c * 32 + j * 16) * KPAD + ks * 8, KPAD);
                #pragma unroll
                for (int t = 0; t < bk[j].num_elements; t++) bk[j].x[t] = wmma::__float_to_tf32(bk[j].x[t]);
            }
            wmma::mma_sync(cs[0], aq[ks], bk[0], cs[0]);
            wmma::mma_sync(cs[1], aq[ks], bk[1], cs[1]);
        }
        wmma::store_matrix_sync(Ss + (warp_r * 16) * SPAD + warp_c * 32,      cs[0], SPAD, wmma::mem_row_major);
        wmma::store_matrix_sync(Ss + (warp_r * 16) * SPAD + warp_c * 32 + 16, cs[1], SPAD, wmma::mem_row_major);
        __syncthreads();

        {   // normalize, write attn to gmem, leave P in Ss
            const float iv = rinv[r];
            #pragma unroll
            for (int i4 = 0; i4 < 4; i4++) {
                int c = c0 + i4 * 16;
                float4 s4 = *(const float4*)(Ss + r * SPAD + c);
                float4 p4;
                p4.x = ms[c + 0] ? __expf(s4.x * 0.125f) * iv : 0.0f;
                p4.y = ms[c + 1] ? __expf(s4.y * 0.125f) * iv : 0.0f;
                p4.z = ms[c + 2] ? __expf(s4.z * 0.125f) * iv : 0.0f;
                p4.w = ms[c + 3] ? __expf(s4.w * 0.125f) * iv : 0.0f;
                *(float4*)(Ss + r * SPAD + c) = p4;
                *(float4*)(attn + attn_base + (size_t)r * LL + kt * 64 + c) = p4;
            }
        }
        __syncthreads();

        // stage V tile into KVs (aliases K tile — S is already consumed)
        #pragma unroll
        for (int j = 0; j < 4; j++) {
            int idx = tid + 256 * j;
            int rr = idx >> 4, c4 = idx & 15;
            *(float4*)(KVs + rr * KPAD + c4 * 4) =
                *(const float4*)(Vb + (size_t)(kt * 64 + rr) * DD + c4 * 4);
        }
        __syncthreads();

        #pragma unroll
        for (int ks = 0; ks < 8; ks++) {
            wmma::fragment<wmma::matrix_a, 16, 16, 8, wmma::precision::tf32, wmma::row_major> ap;
            wmma::load_matrix_sync(ap, Ss + (warp_r * 16) * SPAD + ks * 8, SPAD);
            #pragma unroll
            for (int t = 0; t < ap.num_elements; t++) ap.x[t] = wmma::__float_to_tf32(ap.x[t]);
            wmma::fragment<wmma::matrix_b, 16, 16, 8, wmma::precision::tf32, wmma::row_major> bv[2];
            #pragma unroll
            for (int j = 0; j < 2; j++) {
                wmma::load_matrix_sync(bv[j], KVs + (ks * 8) * KPAD + warp_c * 32 + j * 16, KPAD);
                #pragma unroll
                for (int t = 0; t < bv[j].num_elements; t++) bv[j].x[t] = wmma::__float_to_tf32(bv[j].x[t]);
            }
            wmma::mma_sync(of[0], ap, bv[0], of[0]);
            wmma::mma_sync(of[1], ap, bv[1], of[1]);
        }
        __syncthreads();
    }

    // write O tile
    wmma::store_matrix_sync(Ss + (warp_r * 16) * SPAD + warp_c * 32,      of[0], SPAD, wmma::mem_row_major);
    wmma::store_matrix_sync(Ss + (warp_r * 16) * SPAD + warp_c * 32 + 16, of[1], SPAD, wmma::mem_row_major);
    __syncthreads();
    #pragma unroll
    for (int i4 = 0; i4 < 4; i4++) {
        int c = c0 + i4 * 16;
        float4 o4 = *(const float4*)(Ss + r * SPAD + c);
        *(float4*)(go + (size_t)(b * LL + q0 + r) * DD + h * DKH + c) = o4;
    }
}

// ---------------- launch ----------------
extern "C" void kernel_launch(void* const* d_in, const int* in_sizes, int n_in,
                              void* d_out, int out_size)
{
    const float* q      = (const float*)d_in[0];
    const float* k      = (const float*)d_in[1];
    const float* v      = (const float*)d_in[2];
    const float* semf   = (const float*)d_in[3];
    const int*   mask   = (const int*)  d_in[4];
    const float* w_q    = (const float*)d_in[5];
    const float* b_q    = (const float*)d_in[6];
    const float* w_k    = (const float*)d_in[7];
    const float* b_k    = (const float*)d_in[8];
    const float* w_v    = (const float*)d_in[9];
    const float* b_v    = (const float*)d_in[10];
    const float* w_sem  = (const float*)d_in[11];
    const float* b_sem  = (const float*)d_in[12];
    const float* w_out  = (const float*)d_in[13];
    const float* b_out  = (const float*)d_in[14];

    float* out = (float*)d_out;
    const size_t attn_elems = (size_t)BB * HH * LL * LL;  // 268435456
    size_t attn_off = ((size_t)out_size >= attn_elems) ? (size_t)out_size - attn_elems : 0;
    float* attn = out + attn_off;                          // expected: out (B*L*D) then attn

    float *p_sem, *p_q, *p_k, *p_v, *p_o;
    cudaGetSymbolAddress((void**)&p_sem, g_sem);
    cudaGetSymbolAddress((void**)&p_q,   g_qp);
    cudaGetSymbolAddress((void**)&p_k,   g_kp);
    cudaGetSymbolAddress((void**)&p_v,   g_vp);
    cudaGetSymbolAddress((void**)&p_o,   g_op);

    dim3 gg(GN / GBN, (BB * LL) / GBM);   // (16, 64)

    gemm_tf32_kernel<<<gg, 256>>>(semf, w_sem, b_sem, nullptr, p_sem);
    gemm_tf32_kernel<<<gg, 256>>>(q,    w_q,   b_q,   nullptr, p_q);
    gemm_tf32_kernel<<<gg, 256>>>(k,    w_k,   b_k,   p_sem,   p_k);
    gemm_tf32_kernel<<<gg, 256>>>(v,    w_v,   b_v,   p_sem,   p_v);

    attn_kernel<<<dim3(LL / 64, HH, BB), 256>>>(p_q, p_k, p_v, mask, attn, p_o);

    gemm_tf32_kernel<<<gg, 256>>>(p_o, w_out, b_out, nullptr, out);
}

// round 2
// speedup vs baseline: 1.0822x; 1.0822x over previous
#include <cuda_runtime.h>
#include <mma.h>

using namespace nvcuda;

#define BB 4
#define LL 2048
#define DD 1024
#define HH 16
#define DKH 64

// ---------------- scratch (static device allocations) ----------------
__device__ float g_sem [(size_t)BB * LL * DD];
__device__ float g_qp  [(size_t)BB * LL * DD];
__device__ float g_kp  [(size_t)BB * LL * DD];
__device__ float g_vp  [(size_t)BB * LL * DD];
__device__ float g_op  [(size_t)BB * LL * DD];
__device__ float g_rinv[(size_t)BB * HH * LL];

// ================= multistage tf32 GEMM =================
// C[m,n] = sum_k X[m,k] * W[n,k] + bias[n] (+ addend[m,n])
// X: [M,1024] rm, W: [1024,1024] rm (N x K). Block tile 128x128, BK=16, 4 stages.
#define GK   1024
#define GN   1024
#define BM   128
#define BN   128
#define BKK  16
#define BKP  20
#define NST  4
#define NT   (GK / BKK)      // 64
#define CPADG 132

__device__ __forceinline__ void cpa16(float* dst, const float* src) {
    unsigned saddr = (unsigned)__cvta_generic_to_shared(dst);
    asm volatile("cp.async.cg.shared.global [%0], [%1], 16;\n" :: "r"(saddr), "l"(src));
}

__global__ __launch_bounds__(256) void gemm2(
    const float* __restrict__ X, const float* __restrict__ W,
    const float* __restrict__ bias, const float* __restrict__ addend,
    float* __restrict__ C)
{
    extern __shared__ float sm[];
    const int tid = threadIdx.x;
    const int wid = tid >> 5;
    const int warp_m = wid & 3;     // 4 row groups of 32
    const int warp_n = wid >> 2;    // 2 col groups of 64
    const int m0 = blockIdx.y * BM;
    const int n0 = blockIdx.x * BN;

    wmma::fragment<wmma::accumulator, 16, 16, 8, float> c[2][4];
    #pragma unroll
    for (int i = 0; i < 2; i++)
        #pragma unroll
        for (int j = 0; j < 4; j++) wmma::fill_fragment(c[i][j], 0.0f);

    // prologue: stages 0..NST-2
    #pragma unroll
    for (int s = 0; s < NST - 1; s++) {
        float* Xs = sm + s * (BM + BN) * BKP;
        float* Ws = Xs + BM * BKP;
        const int k0 = s * BKK;
        #pragma unroll
        for (int j = 0; j < 2; j++) {
            int idx = tid + 256 * j;
            int r = idx >> 2, cc = (idx & 3) * 4;
            cpa16(Xs + r * BKP + cc, X + (size_t)(m0 + r) * GK + k0 + cc);
            cpa16(Ws + r * BKP + cc, W + (size_t)(n0 + r) * GK + k0 + cc);
        }
        asm volatile("cp.async.commit_group;\n");
    }

    for (int kt = 0; kt < NT; kt++) {
        asm volatile("cp.async.wait_group %0;\n" :: "n"(NST - 2));
        __syncthreads();

        // top up pipeline (buffer (kt-1)%NST is free after the barrier above)
        const int ldkt = kt + NST - 1;
        if (ldkt < NT) {
            float* Xs = sm + (ldkt % NST) * (BM + BN) * BKP;
            float* Ws = Xs + BM * BKP;
            const int k0 = ldkt * BKK;
            #pragma unroll
            for (int j = 0; j < 2; j++) {
                int idx = tid + 256 * j;
                int r = idx >> 2, cc = (idx & 3) * 4;
                cpa16(Xs + r * BKP + cc, X + (size_t)(m0 + r) * GK + k0 + cc);
                cpa16(Ws + r * BKP + cc, W + (size_t)(n0 + r) * GK + k0 + cc);
            }
        }
        asm volatile("cp.async.commit_group;\n");

        // compute stage kt
        float* Xs = sm + (kt % NST) * (BM + BN) * BKP;
        float* Ws = Xs + BM * BKP;
        #pragma unroll
        for (int kk = 0; kk < BKK; kk += 8) {
            wmma::fragment<wmma::matrix_a, 16, 16, 8, wmma::precision::tf32, wmma::row_major> a[2];
            wmma::fragment<wmma::matrix_b, 16, 16, 8, wmma::precision::tf32, wmma::col_major> b[4];
            #pragma unroll
            for (int i = 0; i < 2; i++) {
                wmma::load_matrix_sync(a[i], Xs + (warp_m * 32 + i * 16) * BKP + kk, BKP);
                #pragma unroll
                for (int t = 0; t < a[i].num_elements; t++) a[i].x[t] = wmma::__float_to_tf32(a[i].x[t]);
            }
            #pragma unroll
            for (int j = 0; j < 4; j++) {
                wmma::load_matrix_sync(b[j], Ws + (warp_n * 64 + j * 16) * BKP + kk, BKP);
                #pragma unroll
                for (int t = 0; t < b[j].num_elements; t++) b[j].x[t] = wmma::__float_to_tf32(b[j].x[t]);
            }
            #pragma unroll
            for (int i = 0; i < 2; i++)
                #pragma unroll
                for (int j = 0; j < 4; j++) wmma::mma_sync(c[i][j], a[i], b[j], c[i][j]);
        }
    }

    asm volatile("cp.async.wait_group 0;\n");
    __syncthreads();

    // epilogue through smem
    float* Cs = sm;
    #pragma unroll
    for (int i = 0; i < 2; i++)
        #pragma unroll
        for (int j = 0; j < 4; j++)
            wmma::store_matrix_sync(Cs + (warp_m * 32 + i * 16) * CPADG + warp_n * 64 + j * 16,
                                    c[i][j], CPADG, wmma::mem_row_major);
    __syncthreads();

    const int c4 = (tid & 31) * 4;
    const int r0 = tid >> 5;
    float4 bv = *(const float4*)(bias + n0 + c4);
    if (addend) {
        #pragma unroll
        for (int it = 0; it < 16; it++) {
            int r = r0 + it * 8;
            size_t gi = (size_t)(m0 + r) * GN + n0 + c4;
            float4 val = *(const float4*)(Cs + r * CPADG + c4);
            float4 ad = *(const float4*)(addend + gi);
            val.x += bv.x + ad.x; val.y += bv.y + ad.y;
            val.z += bv.z + ad.z; val.w += bv.w + ad.w;
            *(float4*)(C + gi) = val;
        }
    } else {
        #pragma unroll
        for (int it = 0; it < 16; it++) {
            int r = r0 + it * 8;
            size_t gi = (size_t)(m0 + r) * GN + n0 + c4;
            float4 val = *(const float4*)(Cs + r * CPADG + c4);
            val.x += bv.x; val.y += bv.y; val.z += bv.z; val.w += bv.w;
            *(float4*)(C + gi) = val;
        }
    }
}

// ================= one-pass attention =================
// per (b, h, q-tile of 64): for each k-tile: S = QK^T (tf32), p = mask ? exp(S/8) : 0,
// write UNNORMALIZED p to attn, accumulate rowsum (registers) and O += p*V.
// End: O *= 1/rowsum, store rinv for the rescale kernel.
#define KPAD 68
#define SPAD 72

__global__ __launch_bounds__(256) void attn_kernel(
    const float* __restrict__ gq, const float* __restrict__ gk, const float* __restrict__ gv,
    const int* __restrict__ mask, float* __restrict__ attn, float* __restrict__ go,
    float* __restrict__ rinv_out)
{
    __shared__ float KVs[64 * KPAD];
    __shared__ float Ss [64 * SPAD];
    __shared__ int   ms[64];

    const int tid = threadIdx.x;
    const int wid = tid >> 5;
    const int warp_r = wid >> 1;       // 4 groups: 16 q-rows each
    const int warp_c = wid & 1;        // 2 groups: 32 cols each
    const int b = blockIdx.z, h = blockIdx.y;
    const int q0 = blockIdx.x * 64;

    const float* Qb = gq + ((size_t)(b * LL + q0)) * DD + h * DKH;
    const float* Kb = gk + ((size_t)(b * LL)) * DD + h * DKH;
    const float* Vb = gv + ((size_t)(b * LL)) * DD + h * DKH;

    // preload Q a-fragments (constant across all k-tiles)
    wmma::fragment<wmma::matrix_a, 16, 16, 8, wmma::precision::tf32, wmma::row_major> aq[8];
    #pragma unroll
    for (int ks = 0; ks < 8; ks++) {
        wmma::load_matrix_sync(aq[ks], Qb + (size_t)(warp_r * 16) * DD + ks * 8, DD);
        #pragma unroll
        for (int t = 0; t < aq[ks].num_elements; t++) aq[ks].x[t] = wmma::__float_to_tf32(aq[ks].x[t]);
    }

    const int r  = tid >> 2;            // q-row for elementwise steps
    const int c0 = (tid & 3) * 4;       // float4 column base
    const int mbase = b * LL;
    const size_t attn_base = ((size_t)(b * HH + h) * LL + q0) * LL;

    wmma::fragment<wmma::accumulator, 16, 16, 8, float> of[2];
    wmma::fill_fragment(of[0], 0.0f);
    wmma::fill_fragment(of[1], 0.0f);

    float racc = 0.0f;                  // per-thread partial rowsum

    for (int kt = 0; kt < 32; kt++) {
        // stage K tile
        #pragma unroll
        for (int j = 0; j < 4; j++) {
            int idx = tid + 256 * j;
            int rr = idx >> 4, c4 = idx & 15;
            *(float4*)(KVs + rr * KPAD + c4 * 4) =
                *(const float4*)(Kb + (size_t)(kt * 64 + rr) * DD + c4 * 4);
        }
        if (tid < 64) ms[tid] = mask[mbase + kt * 64 + tid];
        __syncthreads();   // A: K staged; also guards Ss reuse vs prev PV reads

        // S = Q K^T
        wmma::fragment<wmma::accumulator, 16, 16, 8, float> cs[2];
        wmma::fill_fragment(cs[0], 0.0f);
        wmma::fill_fragment(cs[1], 0.0f);
        #pragma unroll
        for (int ks = 0; ks < 8; ks++) {
            wmma::fragment<wmma::matrix_b, 16, 16, 8, wmma::precision::tf32, wmma::col_major> bk[2];
            #pragma unroll
            for (int j = 0; j < 2; j++) {
                wmma::load_matrix_sync(bk[j], KVs + (warp_c * 32 + j * 16) * KPAD + ks * 8, KPAD);
                #pragma unroll
                for (int t = 0; t < bk[j].num_elements; t++) bk[j].x[t] = wmma::__float_to_tf32(bk[j].x[t]);
            }
            wmma::mma_sync(cs[0], aq[ks], bk[0], cs[0]);
            wmma::mma_sync(cs[1], aq[ks], bk[1], cs[1]);
        }
        wmma::store_matrix_sync(Ss + (warp_r * 16) * SPAD + warp_c * 32,      cs[0], SPAD, wmma::mem_row_major);
        wmma::store_matrix_sync(Ss + (warp_r * 16) * SPAD + warp_c * 32 + 16, cs[1], SPAD, wmma::mem_row_major);
        __syncthreads();   // B: S visible

        // p = exp(masked S), write unnormalized attn, keep P in Ss, accumulate rowsum
        #pragma unroll
        for (int i4 = 0; i4 < 4; i4++) {
            int c = c0 + i4 * 16;
            float4 s4 = *(const float4*)(Ss + r * SPAD + c);
            float4 p4;
            p4.x = ms[c + 0] ? __expf(s4.x * 0.125f) : 0.0f;
            p4.y = ms[c + 1] ? __expf(s4.y * 0.125f) : 0.0f;
            p4.z = ms[c + 2] ? __expf(s4.z * 0.125f) : 0.0f;
            p4.w = ms[c + 3] ? __expf(s4.w * 0.125f) : 0.0f;
            racc += p4.x + p4.y + p4.z + p4.w;
            *(float4*)(Ss + r * SPAD + c) = p4;
            *(float4*)(attn + attn_base + (size_t)r * LL + kt * 64 + c) = p4;
        }
        // stage V tile (K consumed)
        #pragma unroll
        for (int j = 0; j < 4; j++) {
            int idx = tid + 256 * j;
            int rr = idx >> 4, c4 = idx & 15;
            *(float4*)(KVs + rr * KPAD + c4 * 4) =
                *(const float4*)(Vb + (size_t)(kt * 64 + rr) * DD + c4 * 4);
        }
        __syncthreads();   // C: P + V staged

        // O += P V
        #pragma unroll
        for (int ks = 0; ks < 8; ks++) {
            wmma::fragment<wmma::matrix_a, 16, 16, 8, wmma::precision::tf32, wmma::row_major> ap;
            wmma::load_matrix_sync(ap, Ss + (warp_r * 16) * SPAD + ks * 8, SPAD);
            #pragma unroll
            for (int t = 0; t < ap.num_elements; t++) ap.x[t] = wmma::__float_to_tf32(ap.x[t]);
            wmma::fragment<wmma::matrix_b, 16, 16, 8, wmma::precision::tf32, wmma::row_major> bv[2];
            #pragma unroll
            for (int j = 0; j < 2; j++) {
                wmma::load_matrix_sync(bv[j], KVs + (ks * 8) * KPAD + warp_c * 32 + j * 16, KPAD);
                #pragma unroll
                for (int t = 0; t < bv[j].num_elements; t++) bv[j].x[t] = wmma::__float_to_tf32(bv[j].x[t]);
            }
            wmma::mma_sync(of[0], ap, bv[0], of[0]);
            wmma::mma_sync(of[1], ap, bv[1], of[1]);
        }
        __syncthreads();   // D: PV reads done before next K overwrite
    }

    // rowsum across the 4 threads of each row
    racc += __shfl_xor_sync(0xffffffff, racc, 1);
    racc += __shfl_xor_sync(0xffffffff, racc, 2);
    const float rv = 1.0f / racc;
    if ((tid & 3) == 0) rinv_out[(size_t)(b * HH + h) * LL + q0 + r] = rv;

    // O epilogue: scale by rinv, write
    wmma::store_matrix_sync(Ss + (warp_r * 16) * SPAD + warp_c * 32,      of[0], SPAD, wmma::mem_row_major);
    wmma::store_matrix_sync(Ss + (warp_r * 16) * SPAD + warp_c * 32 + 16, of[1], SPAD, wmma::mem_row_major);
    __syncthreads();
    #pragma unroll
    for (int i4 = 0; i4 < 4; i4++) {
        int c = c0 + i4 * 16;
        float4 o4 = *(const float4*)(Ss + r * SPAD + c);
        o4.x *= rv; o4.y *= rv; o4.z *= rv; o4.w *= rv;
        *(float4*)(go + (size_t)(b * LL + q0 + r) * DD + h * DKH + c) = o4;
    }
}

// ================= attn normalization (in place) =================
__global__ __launch_bounds__(256) void rescale_kernel(
    float4* __restrict__ attn4, const float* __restrict__ rinv)
{
    size_t base = (size_t)blockIdx.x * 512 + threadIdx.x;
    #pragma unroll
    for (int j = 0; j < 2; j++) {
        size_t f = base + (size_t)j * 256;
        float s = __ldg(rinv + (f >> 9));          // 512 float4 per row of L=2048
        float4 v = attn4[f];
        v.x *= s; v.y *= s; v.z *= s; v.w *= s;
        attn4[f] = v;
    }
}

// ================= launch =================
extern "C" void kernel_launch(void* const* d_in, const int* in_sizes, int n_in,
                              void* d_out, int out_size)
{
    const float* q      = (const float*)d_in[0];
    const float* k      = (const float*)d_in[1];
    const float* v      = (const float*)d_in[2];
    const float* semf   = (const float*)d_in[3];
    const int*   mask   = (const int*)  d_in[4];
    const float* w_q    = (const float*)d_in[5];
    const float* b_q    = (const float*)d_in[6];
    const float* w_k    = (const float*)d_in[7];
    const float* b_k    = (const float*)d_in[8];
    const float* w_v    = (const float*)d_in[9];
    const float* b_v    = (const float*)d_in[10];
    const float* w_sem  = (const float*)d_in[11];
    const float* b_sem  = (const float*)d_in[12];
    const float* w_out  = (const float*)d_in[13];
    const float* b_out  = (const float*)d_in[14];

    float* out = (float*)d_out;
    const size_t attn_elems = (size_t)BB * HH * LL * LL;  // 268435456
    size_t attn_off = ((size_t)out_size >= attn_elems) ? (size_t)out_size - attn_elems : 0;
    float* attn = out + attn_off;

    float *p_sem, *p_q, *p_k, *p_v, *p_o, *p_ri;
    cudaGetSymbolAddress((void**)&p_sem, g_sem);
    cudaGetSymbolAddress((void**)&p_q,   g_qp);
    cudaGetSymbolAddress((void**)&p_k,   g_kp);
    cudaGetSymbolAddress((void**)&p_v,   g_vp);
    cudaGetSymbolAddress((void**)&p_o,   g_op);
    cudaGetSymbolAddress((void**)&p_ri,  g_rinv);

    const int smem_bytes = NST * (BM + BN) * BKP * 4;   // 81920
    cudaFuncSetAttribute(gemm2, cudaFuncAttributeMaxDynamicSharedMemorySize, smem_bytes);

    dim3 gg(GN / BN, (BB * LL) / BM);   // (8, 64)

    gemm2<<<gg, 256, smem_bytes>>>(semf, w_sem, b_sem, nullptr, p_sem);
    gemm2<<<gg, 256, smem_bytes>>>(q,    w_q,   b_q,   nullptr, p_q);
    gemm2<<<gg, 256, smem_bytes>>>(k,    w_k,   b_k,   p_sem,   p_k);
    gemm2<<<gg, 256, smem_bytes>>>(v,    w_v,   b_v,   p_sem,   p_v);

    attn_kernel<<<dim3(LL / 64, HH, BB), 256>>>(p_q, p_k, p_v, mask, attn, p_o, p_ri);

    rescale_kernel<<<(unsigned)(attn_elems / 4 / 512), 256>>>((float4*)attn, p_ri);

    gemm2<<<gg, 256, smem_bytes>>>(p_o, w_out, b_out, nullptr, out);
}

// round 5
// speedup vs baseline: 2.9163x; 2.6949x over previous
#include <cuda_runtime.h>
#include <cuda_fp16.h>
#include <mma.h>
#include <cstdint>

using namespace nvcuda;

#define BB 4
#define LL 2048
#define DD 1024
#define HH 16
#define DKH 64
#define GK 1024
#define GN 1024

// ---------------- bitcast helpers (no __half2_as_uint in this toolkit) ----------------
__device__ __forceinline__ uint32_t h2u(__half2 h) {
    uint32_t u;
    *reinterpret_cast<__half2*>(&u) = h;
    return u;
}
__device__ __forceinline__ __half2 u2h(uint32_t u) {
    return *reinterpret_cast<__half2*>(&u);
}

// ---------------- scratch (static device allocations) ----------------
__device__ __half g_qx  [(size_t)BB * LL * DD];   // converted inputs
__device__ __half g_kx  [(size_t)BB * LL * DD];
__device__ __half g_vx  [(size_t)BB * LL * DD];
__device__ __half g_sx  [(size_t)BB * LL * DD];   // semantic_feat (SEM=1024)
__device__ __half g_wq  [(size_t)DD * DD];
__device__ __half g_wk  [(size_t)DD * DD];
__device__ __half g_wv  [(size_t)DD * DD];
__device__ __half g_ws  [(size_t)DD * DD];
__device__ __half g_wo  [(size_t)DD * DD];
__device__ __half g_semo[(size_t)BB * LL * DD];   // sem projection (addend)
__device__ __half g_qp  [(size_t)BB * LL * DD];
__device__ __half g_kp  [(size_t)BB * LL * DD];
__device__ __half g_vp  [(size_t)BB * LL * DD];
__device__ __half g_op  [(size_t)BB * LL * DD];   // attention output O
__device__ __half g_ps  [(size_t)BB * HH * LL * LL]; // unnormalized P (536MB)
__device__ float  g_rinv[(size_t)BB * HH * LL];

// ================= f32 -> f16 conversion =================
__global__ __launch_bounds__(256) void cvt_kernel(const float4* __restrict__ in,
                                                  uint4* __restrict__ out)
{
    size_t i = (size_t)blockIdx.x * 256 + threadIdx.x;   // per 8 elements
    float4 a = in[i * 2], b = in[i * 2 + 1];
    uint4 o;
    o.x = h2u(__floats2half2_rn(a.x, a.y));
    o.y = h2u(__floats2half2_rn(a.z, a.w));
    o.z = h2u(__floats2half2_rn(b.x, b.y));
    o.w = h2u(__floats2half2_rn(b.z, b.w));
    out[i] = o;
}

// ================= fp16 GEMM (HMMA 16x16x16, fp32 accum) =================
// C[m,n] = sum_k X[m,k]*W[n,k] + bias[n] (+ addend[m,n]); X,W half; C = OutT
#define HBM 128
#define HBN 64
#define HBK 32
#define HPAD 40          // row stride in halves (80B)
#define HNST 4
#define HNT (GK / HBK)   // 32
#define HSTG ((HBM + HBN) * HPAD)       // halves per stage: 7680
#define HCPAD 68
#define HSMEM_BYTES (HNST * HSTG * 2)   // 61440

__device__ __forceinline__ void cpa16h(uint32_t saddr, const __half* src) {
    asm volatile("cp.async.cg.shared.global [%0], [%1], 16;\n" :: "r"(saddr), "l"(src));
}
__device__ __forceinline__ uint32_t smem_u32(const void* p) {
    uint32_t a;
    asm("{ .reg .u64 t; cvta.to.shared.u64 t, %1; cvt.u32.u64 %0, t; }" : "=r"(a) : "l"(p));
    return a;
}

template <typename OutT, bool HASADD>
__global__ __launch_bounds__(256) void gemm_h(
    const __half* __restrict__ X, const __half* __restrict__ W,
    const float* __restrict__ bias, const __half* __restrict__ addend,
    OutT* __restrict__ C)
{
    extern __shared__ __half hsm[];
    const int tid = threadIdx.x;
    const int wid = tid >> 5;
    const int warp_m = wid & 3;      // 4 groups of 32 rows
    const int warp_n = wid >> 2;     // 2 groups of 32 cols
    const int m0 = blockIdx.y * HBM;
    const int n0 = blockIdx.x * HBN;
    const uint32_t smb = smem_u32(hsm);

    wmma::fragment<wmma::accumulator, 16, 16, 16, float> c[2][2];
    #pragma unroll
    for (int i = 0; i < 2; i++)
        #pragma unroll
        for (int j = 0; j < 2; j++) wmma::fill_fragment(c[i][j], 0.0f);

    // per-stage copy: 768 chunks of 16B (A:512, B:256)
    auto stage = [&](int s, int k0) {
        uint32_t base = smb + (uint32_t)(s * HSTG) * 2;
        #pragma unroll
        for (int j = 0; j < 3; j++) {
            int idx = tid + 256 * j;
            if (idx < 512) {
                int r = idx >> 2, c8 = (idx & 3) * 8;
                cpa16h(base + (uint32_t)(r * HPAD + c8) * 2,
                       X + (size_t)(m0 + r) * GK + k0 + c8);
            } else {
                int i2 = idx - 512;
                int r = i2 >> 2, c8 = (i2 & 3) * 8;
                cpa16h(base + (uint32_t)((HBM + r) * HPAD + c8) * 2,
                       W + (size_t)(n0 + r) * GK + k0 + c8);
            }
        }
        asm volatile("cp.async.commit_group;\n");
    };

    #pragma unroll
    for (int s = 0; s < HNST - 1; s++) stage(s, s * HBK);

    for (int kt = 0; kt < HNT; kt++) {
        asm volatile("cp.async.wait_group %0;\n" :: "n"(HNST - 2));
        __syncthreads();

        const int ld = kt + HNST - 1;
        if (ld < HNT) stage(ld % HNST, ld * HBK);
        else asm volatile("cp.async.commit_group;\n");

        const __half* Xs = hsm + (kt % HNST) * HSTG;
        const __half* Ws = Xs + HBM * HPAD;
        #pragma unroll
        for (int kk = 0; kk < HBK; kk += 16) {
            wmma::fragment<wmma::matrix_a, 16, 16, 16, __half, wmma::row_major> a[2];
            wmma::fragment<wmma::matrix_b, 16, 16, 16, __half, wmma::col_major> b[2];
            #pragma unroll
            for (int i = 0; i < 2; i++)
                wmma::load_matrix_sync(a[i], Xs + (warp_m * 32 + i * 16) * HPAD + kk, HPAD);
            #pragma unroll
            for (int j = 0; j < 2; j++)
                wmma::load_matrix_sync(b[j], Ws + (warp_n * 32 + j * 16) * HPAD + kk, HPAD);
            #pragma unroll
            for (int i = 0; i < 2; i++)
                #pragma unroll
                for (int j = 0; j < 2; j++) wmma::mma_sync(c[i][j], a[i], b[j], c[i][j]);
        }
    }

    asm volatile("cp.async.wait_group 0;\n");
    __syncthreads();

    // epilogue via smem (f32)
    float* Cs = (float*)hsm;    // [128][HCPAD] = 34.8KB < 61.4KB
    #pragma unroll
    for (int i = 0; i < 2; i++)
        #pragma unroll
        for (int j = 0; j < 2; j++)
            wmma::store_matrix_sync(Cs + (warp_m * 32 + i * 16) * HCPAD + warp_n * 32 + j * 16,
                                    c[i][j], HCPAD, wmma::mem_row_major);
    __syncthreads();

    const int c4 = (tid & 15) * 4;      // 16 threads cover 64 cols
    const int r0 = tid >> 4;            // 16 row starts
    float4 bv = *(const float4*)(bias + n0 + c4);
    #pragma unroll
    for (int it = 0; it < 8; it++) {
        int rr = r0 + it * 16;
        size_t gi = (size_t)(m0 + rr) * GN + n0 + c4;
        float4 val = *(const float4*)(Cs + rr * HCPAD + c4);
        val.x += bv.x; val.y += bv.y; val.z += bv.z; val.w += bv.w;
        if (HASADD) {
            uint2 au = *(const uint2*)(addend + gi);
            __half2 a01 = u2h(au.x), a23 = u2h(au.y);
            val.x += __low2float(a01);  val.y += __high2float(a01);
            val.z += __low2float(a23);  val.w += __high2float(a23);
        }
        if (sizeof(OutT) == 2) {
            uint2 o;
            o.x = h2u(__floats2half2_rn(val.x, val.y));
            o.y = h2u(__floats2half2_rn(val.z, val.w));
            *(uint2*)((__half*)C + gi) = o;
        } else {
            *(float4*)((float*)C + gi) = val;
        }
    }
}

// ================= one-pass fp16 attention =================
// per (b,h,q-tile 64): S = QK^T (fp16 mma, f32 acc); p = mask ? exp(S/8) : 0;
// write p (half) to g_ps; O += pV; end: O *= 1/rowsum (stored for rescale).
#define AKP 72     // half row stride for K/V and P tiles
#define ASP 72     // f32 row stride for S

__global__ __launch_bounds__(256) void attn_kernel(
    const __half* __restrict__ gq, const __half* __restrict__ gk, const __half* __restrict__ gv,
    const int* __restrict__ mask, __half* __restrict__ ps, __half* __restrict__ go,
    float* __restrict__ rinv_out)
{
    __shared__ __half KVs[64 * AKP];
    __shared__ __half Ps [64 * AKP];
    __shared__ float  Ss [64 * ASP];
    __shared__ int    ms[64];

    const int tid = threadIdx.x;
    const int wid = tid >> 5;
    const int warp_r = wid >> 1;       // 4 groups of 16 q-rows
    const int warp_c = wid & 1;        // 2 groups of 32 cols
    const int b = blockIdx.z, h = blockIdx.y;
    const int q0 = blockIdx.x * 64;

    const __half* Qb = gq + ((size_t)(b * LL + q0)) * DD + h * DKH;
    const __half* Kb = gk + ((size_t)(b * LL)) * DD + h * DKH;
    const __half* Vb = gv + ((size_t)(b * LL)) * DD + h * DKH;

    // Q a-frags: 4 k-steps of 16 over DK=64, constant across k-tiles
    wmma::fragment<wmma::matrix_a, 16, 16, 16, __half, wmma::row_major> aq[4];
    #pragma unroll
    for (int ks = 0; ks < 4; ks++)
        wmma::load_matrix_sync(aq[ks], Qb + (size_t)(warp_r * 16) * DD + ks * 16, DD);

    const int r  = tid >> 2;
    const int c0 = (tid & 3) * 4;
    const int mbase = b * LL;
    const size_t ps_base = ((size_t)(b * HH + h) * LL + q0) * LL;

    wmma::fragment<wmma::accumulator, 16, 16, 16, float> of[2];
    wmma::fill_fragment(of[0], 0.0f);
    wmma::fill_fragment(of[1], 0.0f);

    float racc = 0.0f;

    for (int kt = 0; kt < 32; kt++) {
        // stage K tile: 64 rows x 64 halves (128B) = 512 x 16B chunks
        #pragma unroll
        for (int j = 0; j < 2; j++) {
            int idx = tid + 256 * j;
            int rr = idx >> 3, c8 = (idx & 7) * 8;
            *(uint4*)(KVs + rr * AKP + c8) =
                *(const uint4*)(Kb + (size_t)(kt * 64 + rr) * DD + c8);
        }
        if (tid < 64) ms[tid] = mask[mbase + kt * 64 + tid];
        __syncthreads();

        // S = Q K^T
        wmma::fragment<wmma::accumulator, 16, 16, 16, float> cs[2];
        wmma::fill_fragment(cs[0], 0.0f);
        wmma::fill_fragment(cs[1], 0.0f);
        #pragma unroll
        for (int ks = 0; ks < 4; ks++) {
            wmma::fragment<wmma::matrix_b, 16, 16, 16, __half, wmma::col_major> bk[2];
            #pragma unroll
            for (int j = 0; j < 2; j++)
                wmma::load_matrix_sync(bk[j], KVs + (warp_c * 32 + j * 16) * AKP + ks * 16, AKP);
            wmma::mma_sync(cs[0], aq[ks], bk[0], cs[0]);
            wmma::mma_sync(cs[1], aq[ks], bk[1], cs[1]);
        }
        wmma::store_matrix_sync(Ss + (warp_r * 16) * ASP + warp_c * 32,      cs[0], ASP, wmma::mem_row_major);
        wmma::store_matrix_sync(Ss + (warp_r * 16) * ASP + warp_c * 32 + 16, cs[1], ASP, wmma::mem_row_major);
        __syncthreads();

        // p = exp(masked S); keep half P in smem; write half P to gmem
        #pragma unroll
        for (int i4 = 0; i4 < 4; i4++) {
            int c = c0 + i4 * 16;
            float4 s4 = *(const float4*)(Ss + r * ASP + c);
            float4 p4;
            p4.x = ms[c + 0] ? __expf(s4.x * 0.125f) : 0.0f;
            p4.y = ms[c + 1] ? __expf(s4.y * 0.125f) : 0.0f;
            p4.z = ms[c + 2] ? __expf(s4.z * 0.125f) : 0.0f;
            p4.w = ms[c + 3] ? __expf(s4.w * 0.125f) : 0.0f;
            racc += p4.x + p4.y + p4.z + p4.w;
            uint2 hp;
            hp.x = h2u(__floats2half2_rn(p4.x, p4.y));
            hp.y = h2u(__floats2half2_rn(p4.z, p4.w));
            *(uint2*)(Ps + r * AKP + c) = hp;
            *(uint2*)(ps + ps_base + (size_t)r * LL + kt * 64 + c) = hp;
        }
        // stage V tile (K consumed by MMA above)
        #pragma unroll
        for (int j = 0; j < 2; j++) {
            int idx = tid + 256 * j;
            int rr = idx >> 3, c8 = (idx & 7) * 8;
            *(uint4*)(KVs + rr * AKP + c8) =
                *(const uint4*)(Vb + (size_t)(kt * 64 + rr) * DD + c8);
        }
        __syncthreads();

        // O += P V
        #pragma unroll
        for (int ks = 0; ks < 4; ks++) {
            wmma::fragment<wmma::matrix_a, 16, 16, 16, __half, wmma::row_major> ap;
            wmma::load_matrix_sync(ap, Ps + (warp_r * 16) * AKP + ks * 16, AKP);
            wmma::fragment<wmma::matrix_b, 16, 16, 16, __half, wmma::row_major> bv[2];
            #pragma unroll
            for (int j = 0; j < 2; j++)
                wmma::load_matrix_sync(bv[j], KVs + (ks * 16) * AKP + warp_c * 32 + j * 16, AKP);
            wmma::mma_sync(of[0], ap, bv[0], of[0]);
            wmma::mma_sync(of[1], ap, bv[1], of[1]);
        }
        __syncthreads();
    }

    racc += __shfl_xor_sync(0xffffffff, racc, 1);
    racc += __shfl_xor_sync(0xffffffff, racc, 2);
    const float rv = 1.0f / racc;
    if ((tid & 3) == 0) rinv_out[(size_t)(b * HH + h) * LL + q0 + r] = rv;

    // O epilogue
    wmma::store_matrix_sync(Ss + (warp_r * 16) * ASP + warp_c * 32,      of[0], ASP, wmma::mem_row_major);
    wmma::store_matrix_sync(Ss + (warp_r * 16) * ASP + warp_c * 32 + 16, of[1], ASP, wmma::mem_row_major);
    __syncthreads();
    #pragma unroll
    for (int i4 = 0; i4 < 4; i4++) {
        int c = c0 + i4 * 16;
        float4 o4 = *(const float4*)(Ss + r * ASP + c);
        uint2 ho;
        ho.x = h2u(__floats2half2_rn(o4.x * rv, o4.y * rv));
        ho.y = h2u(__floats2half2_rn(o4.z * rv, o4.w * rv));
        *(uint2*)(go + (size_t)(b * LL + q0 + r) * DD + h * DKH + c) = ho;
    }
}

// ================= rescale: half P -> normalized f32 attn =================
__global__ __launch_bounds__(256) void rescale_kernel(
    const uint4* __restrict__ ps4, const float* __restrict__ rinv,
    float4* __restrict__ attn4)
{
    size_t f = (size_t)blockIdx.x * 256 + threadIdx.x;   // per 8 elements
    float s = __ldg(rinv + (f >> 8));                    // 256 x 8 halves per row
    uint4 u = ps4[f];
    __half2 h0 = u2h(u.x), h1 = u2h(u.y);
    __half2 h2v = u2h(u.z), h3 = u2h(u.w);
    float4 o0, o1;
    o0.x = __low2float(h0) * s;  o0.y = __high2float(h0) * s;
    o0.z = __low2float(h1) * s;  o0.w = __high2float(h1) * s;
    o1.x = __low2float(h2v) * s; o1.y = __high2float(h2v) * s;
    o1.z = __low2float(h3) * s;  o1.w = __high2float(h3) * s;
    attn4[f * 2]     = o0;
    attn4[f * 2 + 1] = o1;
}

// ================= launch =================
extern "C" void kernel_launch(void* const* d_in, const int* in_sizes, int n_in,
                              void* d_out, int out_size)
{
    const float* q      = (const float*)d_in[0];
    const float* k      = (const float*)d_in[1];
    const float* v      = (const float*)d_in[2];
    const float* semf   = (const float*)d_in[3];
    const int*   mask   = (const int*)  d_in[4];
    const float* w_q    = (const float*)d_in[5];
    const float* b_q    = (const float*)d_in[6];
    const float* w_k    = (const float*)d_in[7];
    const float* b_k    = (const float*)d_in[8];
    const float* w_v    = (const float*)d_in[9];
    const float* b_v    = (const float*)d_in[10];
    const float* w_sem  = (const float*)d_in[11];
    const float* b_sem  = (const float*)d_in[12];
    const float* w_out  = (const float*)d_in[13];
    const float* b_out  = (const float*)d_in[14];

    float* out = (float*)d_out;
    const size_t attn_elems = (size_t)BB * HH * LL * LL;
    size_t attn_off = ((size_t)out_size >= attn_elems) ? (size_t)out_size - attn_elems : 0;
    float* attn = out + attn_off;

    __half *p_qx, *p_kx, *p_vx, *p_sx, *p_wq, *p_wk, *p_wv, *p_ws, *p_wo;
    __half *p_semo, *p_qp, *p_kp, *p_vp, *p_op, *p_ps;
    float *p_ri;
    cudaGetSymbolAddress((void**)&p_qx, g_qx);
    cudaGetSymbolAddress((void**)&p_kx, g_kx);
    cudaGetSymbolAddress((void**)&p_vx, g_vx);
    cudaGetSymbolAddress((void**)&p_sx, g_sx);
    cudaGetSymbolAddress((void**)&p_wq, g_wq);
    cudaGetSymbolAddress((void**)&p_wk, g_wk);
    cudaGetSymbolAddress((void**)&p_wv, g_wv);
    cudaGetSymbolAddress((void**)&p_ws, g_ws);
    cudaGetSymbolAddress((void**)&p_wo, g_wo);
    cudaGetSymbolAddress((void**)&p_semo, g_semo);
    cudaGetSymbolAddress((void**)&p_qp, g_qp);
    cudaGetSymbolAddress((void**)&p_kp, g_kp);
    cudaGetSymbolAddress((void**)&p_vp, g_vp);
    cudaGetSymbolAddress((void**)&p_op, g_op);
    cudaGetSymbolAddress((void**)&p_ps, g_ps);
    cudaGetSymbolAddress((void**)&p_ri, g_rinv);

    const size_t NBL = (size_t)BB * LL * DD;   // 8M
    const size_t NW  = (size_t)DD * DD;        // 1M

    // conversions
    cvt_kernel<<<(unsigned)(NBL / 2048), 256>>>((const float4*)q,    (uint4*)p_qx);
    cvt_kernel<<<(unsigned)(NBL / 2048), 256>>>((const float4*)k,    (uint4*)p_kx);
    cvt_kernel<<<(unsigned)(NBL / 2048), 256>>>((const float4*)v,    (uint4*)p_vx);
    cvt_kernel<<<(unsigned)(NBL / 2048), 256>>>((const float4*)semf, (uint4*)p_sx);
    cvt_kernel<<<(unsigned)(NW  / 2048), 256>>>((const float4*)w_q,  (uint4*)p_wq);
    cvt_kernel<<<(unsigned)(NW  / 2048), 256>>>((const float4*)w_k,  (uint4*)p_wk);
    cvt_kernel<<<(unsigned)(NW  / 2048), 256>>>((const float4*)w_v,  (uint4*)p_wv);
    cvt_kernel<<<(unsigned)(NW  / 2048), 256>>>((const float4*)w_sem,(uint4*)p_ws);
    cvt_kernel<<<(unsigned)(NW  / 2048), 256>>>((const float4*)w_out,(uint4*)p_wo);

    cudaFuncSetAttribute(gemm_h<__half, false>, cudaFuncAttributeMaxDynamicSharedMemorySize, HSMEM_BYTES);
    cudaFuncSetAttribute(gemm_h<__half, true >, cudaFuncAttributeMaxDynamicSharedMemorySize, HSMEM_BYTES);
    cudaFuncSetAttribute(gemm_h<float,  false>, cudaFuncAttributeMaxDynamicSharedMemorySize, HSMEM_BYTES);

    dim3 gg(GN / HBN, (BB * LL) / HBM);   // (16, 64)

    gemm_h<__half, false><<<gg, 256, HSMEM_BYTES>>>(p_sx, p_ws, b_sem, nullptr, p_semo);
    gemm_h<__half, false><<<gg, 256, HSMEM_BYTES>>>(p_qx, p_wq, b_q,   nullptr, p_qp);
    gemm_h<__half, true ><<<gg, 256, HSMEM_BYTES>>>(p_kx, p_wk, b_k,   p_semo,  p_kp);
    gemm_h<__half, true ><<<gg, 256, HSMEM_BYTES>>>(p_vx, p_wv, b_v,   p_semo,  p_vp);

    attn_kernel<<<dim3(LL / 64, HH, BB), 256>>>(p_qp, p_kp, p_vp, mask, p_ps, p_op, p_ri);

    rescale_kernel<<<(unsigned)(attn_elems / 2048), 256>>>((const uint4*)p_ps, p_ri, (float4*)attn);

    gemm_h<float, false><<<gg, 256, HSMEM_BYTES>>>(p_op, p_wo, b_out, nullptr, out);
}

// round 6
// speedup vs baseline: 3.1821x; 1.0911x over previous
#include <cuda_runtime.h>
#include <cuda_fp16.h>
#include <mma.h>
#include <cstdint>

using namespace nvcuda;

#define BB 4
#define LL 2048
#define DD 1024
#define HH 16
#define DKH 64
#define GK 1024
#define GN 1024

// ---------------- bitcast helpers ----------------
__device__ __forceinline__ uint32_t h2u(__half2 h) {
    uint32_t u;
    *reinterpret_cast<__half2*>(&u) = h;
    return u;
}
__device__ __forceinline__ __half2 u2h(uint32_t u) {
    return *reinterpret_cast<__half2*>(&u);
}

// ---------------- scratch (static device allocations) ----------------
__device__ __half g_qx  [(size_t)BB * LL * DD];
__device__ __half g_kx  [(size_t)BB * LL * DD];
__device__ __half g_vx  [(size_t)BB * LL * DD];
__device__ __half g_sx  [(size_t)BB * LL * DD];
__device__ __half g_wq  [(size_t)DD * DD];
__device__ __half g_wk  [(size_t)DD * DD];
__device__ __half g_wv  [(size_t)DD * DD];
__device__ __half g_ws  [(size_t)DD * DD];
__device__ __half g_wo  [(size_t)DD * DD];
__device__ __half g_semo[(size_t)BB * LL * DD];
__device__ __half g_qp  [(size_t)BB * LL * DD];
__device__ __half g_kp  [(size_t)BB * LL * DD];
__device__ __half g_vp  [(size_t)BB * LL * DD];
__device__ __half g_op  [(size_t)BB * LL * DD];
__device__ __half g_ps  [(size_t)BB * HH * LL * LL];  // unnormalized P (half)
__device__ float  g_rinv[(size_t)BB * HH * LL];

// ================= fused f32 -> f16 conversions =================
__device__ __forceinline__ void cvt8(const float4* in, uint4* out, size_t i) {
    float4 a = in[i * 2], b = in[i * 2 + 1];
    uint4 o;
    o.x = h2u(__floats2half2_rn(a.x, a.y));
    o.y = h2u(__floats2half2_rn(a.z, a.w));
    o.z = h2u(__floats2half2_rn(b.x, b.y));
    o.w = h2u(__floats2half2_rn(b.z, b.w));
    out[i] = o;
}

__global__ __launch_bounds__(256) void cvt_inputs(
    const float4* q, const float4* k, const float4* v, const float4* s,
    uint4* oq, uint4* ok, uint4* ov, uint4* os)
{
    size_t i = (size_t)blockIdx.x * 256 + threadIdx.x;
    switch (blockIdx.y) {
        case 0: cvt8(q, oq, i); break;
        case 1: cvt8(k, ok, i); break;
        case 2: cvt8(v, ov, i); break;
        default: cvt8(s, os, i); break;
    }
}

__global__ __launch_bounds__(256) void cvt_weights(
    const float4* w0, const float4* w1, const float4* w2, const float4* w3, const float4* w4,
    uint4* o0, uint4* o1, uint4* o2, uint4* o3, uint4* o4)
{
    size_t i = (size_t)blockIdx.x * 256 + threadIdx.x;
    switch (blockIdx.y) {
        case 0: cvt8(w0, o0, i); break;
        case 1: cvt8(w1, o1, i); break;
        case 2: cvt8(w2, o2, i); break;
        case 3: cvt8(w3, o3, i); break;
        default: cvt8(w4, o4, i); break;
    }
}

// ================= fp16 GEMM, 128x128 tile (HMMA 16x16x16, fp32 accum) =================
#define HBM 128
#define HBN 128
#define HBK 32
#define HPAD 40                         // halves per row (80B)
#define HNST 4
#define HNT (GK / HBK)                  // 32
#define HSTG ((HBM + HBN) * HPAD)       // halves per stage: 10240
#define HCPAD 132
#define HSMEM_BYTES (HNST * HSTG * 2)   // 81920

__device__ __forceinline__ void cpa16h(uint32_t saddr, const __half* src) {
    asm volatile("cp.async.cg.shared.global [%0], [%1], 16;\n" :: "r"(saddr), "l"(src));
}
__device__ __forceinline__ uint32_t smem_u32(const void* p) {
    uint32_t a;
    asm("{ .reg .u64 t; cvta.to.shared.u64 t, %1; cvt.u32.u64 %0, t; }" : "=r"(a) : "l"(p));
    return a;
}

template <typename OutT, bool HASADD>
__global__ __launch_bounds__(256, 2) void gemm_h(
    const __half* __restrict__ X, const __half* __restrict__ W,
    const float* __restrict__ bias, const __half* __restrict__ addend,
    OutT* __restrict__ C)
{
    extern __shared__ __half hsm[];
    const int tid = threadIdx.x;
    const int wid = tid >> 5;
    const int warp_m = wid & 3;      // 4 groups of 32 rows
    const int warp_n = wid >> 2;     // 2 groups of 64 cols
    const int m0 = blockIdx.y * HBM;
    const int n0 = blockIdx.x * HBN;
    const uint32_t smb = smem_u32(hsm);

    wmma::fragment<wmma::accumulator, 16, 16, 16, float> c[2][4];
    #pragma unroll
    for (int i = 0; i < 2; i++)
        #pragma unroll
        for (int j = 0; j < 4; j++) wmma::fill_fragment(c[i][j], 0.0f);

    // per-stage copy: 1024 chunks of 16B (A:512, B:512), 4 per thread
    auto stage = [&](int s, int k0) {
        uint32_t base = smb + (uint32_t)(s * HSTG) * 2;
        #pragma unroll
        for (int j = 0; j < 4; j++) {
            int idx = tid + 256 * j;
            if (idx < 512) {
                int r = idx >> 2, c8 = (idx & 3) * 8;
                cpa16h(base + (uint32_t)(r * HPAD + c8) * 2,
                       X + (size_t)(m0 + r) * GK + k0 + c8);
            } else {
                int i2 = idx - 512;
                int r = i2 >> 2, c8 = (i2 & 3) * 8;
                cpa16h(base + (uint32_t)((HBM + r) * HPAD + c8) * 2,
                       W + (size_t)(n0 + r) * GK + k0 + c8);
            }
        }
        asm volatile("cp.async.commit_group;\n");
    };

    #pragma unroll
    for (int s = 0; s < HNST - 1; s++) stage(s, s * HBK);

    for (int kt = 0; kt < HNT; kt++) {
        asm volatile("cp.async.wait_group %0;\n" :: "n"(HNST - 2));
        __syncthreads();

        const int ld = kt + HNST - 1;
        if (ld < HNT) stage(ld % HNST, ld * HBK);
        else asm volatile("cp.async.commit_group;\n");

        const __half* Xs = hsm + (kt % HNST) * HSTG;
        const __half* Ws = Xs + HBM * HPAD;
        #pragma unroll
        for (int kk = 0; kk < HBK; kk += 16) {
            wmma::fragment<wmma::matrix_a, 16, 16, 16, __half, wmma::row_major> a[2];
            #pragma unroll
            for (int i = 0; i < 2; i++)
                wmma::load_matrix_sync(a[i], Xs + (warp_m * 32 + i * 16) * HPAD + kk, HPAD);
            #pragma unroll
            for (int j = 0; j < 4; j++) {
                wmma::fragment<wmma::matrix_b, 16, 16, 16, __half, wmma::col_major> b;
                wmma::load_matrix_sync(b, Ws + (warp_n * 64 + j * 16) * HPAD + kk, HPAD);
                wmma::mma_sync(c[0][j], a[0], b, c[0][j]);
                wmma::mma_sync(c[1][j], a[1], b, c[1][j]);
            }
        }
    }

    asm volatile("cp.async.wait_group 0;\n");
    __syncthreads();

    // epilogue via smem (f32)
    float* Cs = (float*)hsm;    // [128][HCPAD] = 67584B <= 81920B
    #pragma unroll
    for (int i = 0; i < 2; i++)
        #pragma unroll
        for (int j = 0; j < 4; j++)
            wmma::store_matrix_sync(Cs + (warp_m * 32 + i * 16) * HCPAD + warp_n * 64 + j * 16,
                                    c[i][j], HCPAD, wmma::mem_row_major);
    __syncthreads();

    const int c4 = (tid & 31) * 4;      // 32 threads cover 128 cols
    const int r0 = tid >> 5;            // 8 row starts
    float4 bv = *(const float4*)(bias + n0 + c4);
    #pragma unroll
    for (int it = 0; it < 16; it++) {
        int rr = r0 + it * 8;
        size_t gi = (size_t)(m0 + rr) * GN + n0 + c4;
        float4 val = *(const float4*)(Cs + rr * HCPAD + c4);
        val.x += bv.x; val.y += bv.y; val.z += bv.z; val.w += bv.w;
        if (HASADD) {
            uint2 au = *(const uint2*)(addend + gi);
            __half2 a01 = u2h(au.x), a23 = u2h(au.y);
            val.x += __low2float(a01);  val.y += __high2float(a01);
            val.z += __low2float(a23);  val.w += __high2float(a23);
        }
        if (sizeof(OutT) == 2) {
            uint2 o;
            o.x = h2u(__floats2half2_rn(val.x, val.y));
            o.y = h2u(__floats2half2_rn(val.z, val.w));
            *(uint2*)((__half*)C + gi) = o;
        } else {
            *(float4*)((float*)C + gi) = val;
        }
    }
}

// ================= one-pass fp16 attention =================
#define AKP 72
#define ASP 72
#define EXPC 0.180336880111f   // log2(e) / 8

__global__ __launch_bounds__(256) void attn_kernel(
    const __half* __restrict__ gq, const __half* __restrict__ gk, const __half* __restrict__ gv,
    const int* __restrict__ mask, __half* __restrict__ ps, __half* __restrict__ go,
    float* __restrict__ rinv_out)
{
    __shared__ __half KVs[64 * AKP];
    __shared__ __half Ps [64 * AKP];
    __shared__ float  Ss [64 * ASP];
    __shared__ __half2 msh[32];

    const int tid = threadIdx.x;
    const int wid = tid >> 5;
    const int warp_r = wid >> 1;
    const int warp_c = wid & 1;
    const int b = blockIdx.z, h = blockIdx.y;
    const int q0 = blockIdx.x * 64;

    const __half* Qb = gq + ((size_t)(b * LL + q0)) * DD + h * DKH;
    const __half* Kb = gk + ((size_t)(b * LL)) * DD + h * DKH;
    const __half* Vb = gv + ((size_t)(b * LL)) * DD + h * DKH;

    wmma::fragment<wmma::matrix_a, 16, 16, 16, __half, wmma::row_major> aq[4];
    #pragma unroll
    for (int ks = 0; ks < 4; ks++)
        wmma::load_matrix_sync(aq[ks], Qb + (size_t)(warp_r * 16) * DD + ks * 16, DD);

    const int r  = tid >> 2;
    const int c0 = (tid & 3) * 4;
    const int mbase = b * LL;
    const size_t ps_base = ((size_t)(b * HH + h) * LL + q0) * LL;

    wmma::fragment<wmma::accumulator, 16, 16, 16, float> of[2];
    wmma::fill_fragment(of[0], 0.0f);
    wmma::fill_fragment(of[1], 0.0f);

    float racc = 0.0f;

    for (int kt = 0; kt < 32; kt++) {
        // stage K tile
        #pragma unroll
        for (int j = 0; j < 2; j++) {
            int idx = tid + 256 * j;
            int rr = idx >> 3, c8 = (idx & 7) * 8;
            *(uint4*)(KVs + rr * AKP + c8) =
                *(const uint4*)(Kb + (size_t)(kt * 64 + rr) * DD + c8);
        }
        if (tid < 32) {
            int m0v = mask[mbase + kt * 64 + tid * 2];
            int m1v = mask[mbase + kt * 64 + tid * 2 + 1];
            msh[tid] = __halves2half2(__int2half_rn(m0v), __int2half_rn(m1v));
        }
        __syncthreads();

        // S = Q K^T
        wmma::fragment<wmma::accumulator, 16, 16, 16, float> cs[2];
        wmma::fill_fragment(cs[0], 0.0f);
        wmma::fill_fragment(cs[1], 0.0f);
        #pragma unroll
        for (int ks = 0; ks < 4; ks++) {
            wmma::fragment<wmma::matrix_b, 16, 16, 16, __half, wmma::col_major> bk[2];
            #pragma unroll
            for (int j = 0; j < 2; j++)
                wmma::load_matrix_sync(bk[j], KVs + (warp_c * 32 + j * 16) * AKP + ks * 16, AKP);
            wmma::mma_sync(cs[0], aq[ks], bk[0], cs[0]);
            wmma::mma_sync(cs[1], aq[ks], bk[1], cs[1]);
        }
        wmma::store_matrix_sync(Ss + (warp_r * 16) * ASP + warp_c * 32,      cs[0], ASP, wmma::mem_row_major);
        wmma::store_matrix_sync(Ss + (warp_r * 16) * ASP + warp_c * 32 + 16, cs[1], ASP, wmma::mem_row_major);
        __syncthreads();

        // p = mask * exp2(S * log2e/8) via ex2.approx.f16x2
        #pragma unroll
        for (int i4 = 0; i4 < 4; i4++) {
            int c = c0 + i4 * 16;
            float4 s4 = *(const float4*)(Ss + r * ASP + c);
            uint32_t x01 = h2u(__floats2half2_rn(s4.x * EXPC, s4.y * EXPC));
            uint32_t x23 = h2u(__floats2half2_rn(s4.z * EXPC, s4.w * EXPC));
            uint32_t e01, e23;
            asm("ex2.approx.f16x2 %0, %1;" : "=r"(e01) : "r"(x01));
            asm("ex2.approx.f16x2 %0, %1;" : "=r"(e23) : "r"(x23));
            __half2 p01 = __hmul2(u2h(e01), msh[c >> 1]);
            __half2 p23 = __hmul2(u2h(e23), msh[(c >> 1) + 1]);
            float2 f01 = __half22float2(p01);
            float2 f23 = __half22float2(p23);
            racc += f01.x + f01.y + f23.x + f23.y;
            uint2 hp;
            hp.x = h2u(p01);
            hp.y = h2u(p23);
            *(uint2*)(Ps + r * AKP + c) = hp;
            __stcs((uint2*)(ps + ps_base + (size_t)r * LL + kt * 64 + c), hp);
        }
        // stage V tile (K consumed)
        #pragma unroll
        for (int j = 0; j < 2; j++) {
            int idx = tid + 256 * j;
            int rr = idx >> 3, c8 = (idx & 7) * 8;
            *(uint4*)(KVs + rr * AKP + c8) =
                *(const uint4*)(Vb + (size_t)(kt * 64 + rr) * DD + c8);
        }
        __syncthreads();

        // O += P V
        #pragma unroll
        for (int ks = 0; ks < 4; ks++) {
            wmma::fragment<wmma::matrix_a, 16, 16, 16, __half, wmma::row_major> ap;
            wmma::load_matrix_sync(ap, Ps + (warp_r * 16) * AKP + ks * 16, AKP);
            wmma::fragment<wmma::matrix_b, 16, 16, 16, __half, wmma::row_major> bv[2];
            #pragma unroll
            for (int j = 0; j < 2; j++)
                wmma::load_matrix_sync(bv[j], KVs + (ks * 16) * AKP + warp_c * 32 + j * 16, AKP);
            wmma::mma_sync(of[0], ap, bv[0], of[0]);
            wmma::mma_sync(of[1], ap, bv[1], of[1]);
        }
        __syncthreads();
    }

    racc += __shfl_xor_sync(0xffffffff, racc, 1);
    racc += __shfl_xor_sync(0xffffffff, racc, 2);
    const float rv = 1.0f / racc;
    if ((tid & 3) == 0) rinv_out[(size_t)(b * HH + h) * LL + q0 + r] = rv;

    // O epilogue
    wmma::store_matrix_sync(Ss + (warp_r * 16) * ASP + warp_c * 32,      of[0], ASP, wmma::mem_row_major);
    wmma::store_matrix_sync(Ss + (warp_r * 16) * ASP + warp_c * 32 + 16, of[1], ASP, wmma::mem_row_major);
    __syncthreads();
    #pragma unroll
    for (int i4 = 0; i4 < 4; i4++) {
        int c = c0 + i4 * 16;
        float4 o4 = *(const float4*)(Ss + r * ASP + c);
        uint2 ho;
        ho.x = h2u(__floats2half2_rn(o4.x * rv, o4.y * rv));
        ho.y = h2u(__floats2half2_rn(o4.z * rv, o4.w * rv));
        *(uint2*)(go + (size_t)(b * LL + q0 + r) * DD + h * DKH + c) = ho;
    }
}

// ================= rescale: half P -> normalized f32 attn =================
__global__ __launch_bounds__(256) void rescale_kernel(
    const uint4* __restrict__ ps4, const float* __restrict__ rinv,
    float4* __restrict__ attn4)
{
    size_t f = (size_t)blockIdx.x * 256 + threadIdx.x;   // per 8 elements
    float s = __ldg(rinv + (f >> 8));
    uint4 u = __ldcs(ps4 + f);
    __half2 h0 = u2h(u.x), h1 = u2h(u.y);
    __half2 h2v = u2h(u.z), h3 = u2h(u.w);
    float4 o0, o1;
    o0.x = __low2float(h0) * s;  o0.y = __high2float(h0) * s;
    o0.z = __low2float(h1) * s;  o0.w = __high2float(h1) * s;
    o1.x = __low2float(h2v) * s; o1.y = __high2float(h2v) * s;
    o1.z = __low2float(h3) * s;  o1.w = __high2float(h3) * s;
    __stcs(attn4 + f * 2,     o0);
    __stcs(attn4 + f * 2 + 1, o1);
}

// ================= launch =================
extern "C" void kernel_launch(void* const* d_in, const int* in_sizes, int n_in,
                              void* d_out, int out_size)
{
    const float* q      = (const float*)d_in[0];
    const float* k      = (const float*)d_in[1];
    const float* v      = (const float*)d_in[2];
    const float* semf   = (const float*)d_in[3];
    const int*   mask   = (const int*)  d_in[4];
    const float* w_q    = (const float*)d_in[5];
    const float* b_q    = (const float*)d_in[6];
    const float* w_k    = (const float*)d_in[7];
    const float* b_k    = (const float*)d_in[8];
    const float* w_v    = (const float*)d_in[9];
    const float* b_v    = (const float*)d_in[10];
    const float* w_sem  = (const float*)d_in[11];
    const float* b_sem  = (const float*)d_in[12];
    const float* w_out  = (const float*)d_in[13];
    const float* b_out  = (const float*)d_in[14];

    float* out = (float*)d_out;
    const size_t attn_elems = (size_t)BB * HH * LL * LL;
    size_t attn_off = ((size_t)out_size >= attn_elems) ? (size_t)out_size - attn_elems : 0;
    float* attn = out + attn_off;

    __half *p_qx, *p_kx, *p_vx, *p_sx, *p_wq, *p_wk, *p_wv, *p_ws, *p_wo;
    __half *p_semo, *p_qp, *p_kp, *p_vp, *p_op, *p_ps;
    float *p_ri;
    cudaGetSymbolAddress((void**)&p_qx, g_qx);
    cudaGetSymbolAddress((void**)&p_kx, g_kx);
    cudaGetSymbolAddress((void**)&p_vx, g_vx);
    cudaGetSymbolAddress((void**)&p_sx, g_sx);
    cudaGetSymbolAddress((void**)&p_wq, g_wq);
    cudaGetSymbolAddress((void**)&p_wk, g_wk);
    cudaGetSymbolAddress((void**)&p_wv, g_wv);
    cudaGetSymbolAddress((void**)&p_ws, g_ws);
    cudaGetSymbolAddress((void**)&p_wo, g_wo);
    cudaGetSymbolAddress((void**)&p_semo, g_semo);
    cudaGetSymbolAddress((void**)&p_qp, g_qp);
    cudaGetSymbolAddress((void**)&p_kp, g_kp);
    cudaGetSymbolAddress((void**)&p_vp, g_vp);
    cudaGetSymbolAddress((void**)&p_op, g_op);
    cudaGetSymbolAddress((void**)&p_ps, g_ps);
    cudaGetSymbolAddress((void**)&p_ri, g_rinv);

    const size_t NBL = (size_t)BB * LL * DD;   // 8M
    const size_t NW  = (size_t)DD * DD;        // 1M

    cvt_inputs<<<dim3((unsigned)(NBL / 2048), 4), 256>>>(
        (const float4*)q, (const float4*)k, (const float4*)v, (const float4*)semf,
        (uint4*)p_qx, (uint4*)p_kx, (uint4*)p_vx, (uint4*)p_sx);
    cvt_weights<<<dim3((unsigned)(NW / 2048), 5), 256>>>(
        (const float4*)w_q, (const float4*)w_k, (const float4*)w_v,
        (const float4*)w_sem, (const float4*)w_out,
        (uint4*)p_wq, (uint4*)p_wk, (uint4*)p_wv, (uint4*)p_ws, (uint4*)p_wo);

    cudaFuncSetAttribute(gemm_h<__half, false>, cudaFuncAttributeMaxDynamicSharedMemorySize, HSMEM_BYTES);
    cudaFuncSetAttribute(gemm_h<__half, true >, cudaFuncAttributeMaxDynamicSharedMemorySize, HSMEM_BYTES);
    cudaFuncSetAttribute(gemm_h<float,  false>, cudaFuncAttributeMaxDynamicSharedMemorySize, HSMEM_BYTES);

    dim3 gg(GN / HBN, (BB * LL) / HBM);   // (8, 64)

    gemm_h<__half, false><<<gg, 256, HSMEM_BYTES>>>(p_sx, p_ws, b_sem, nullptr, p_semo);
    gemm_h<__half, false><<<gg, 256, HSMEM_BYTES>>>(p_qx, p_wq, b_q,   nullptr, p_qp);
    gemm_h<__half, true ><<<gg, 256, HSMEM_BYTES>>>(p_kx, p_wk, b_k,   p_semo,  p_kp);
    gemm_h<__half, true ><<<gg, 256, HSMEM_BYTES>>>(p_vx, p_wv, b_v,   p_semo,  p_vp);

    attn_kernel<<<dim3(LL / 64, HH, BB), 256>>>(p_qp, p_kp, p_vp, mask, p_ps, p_op, p_ri);

    rescale_kernel<<<(unsigned)(attn_elems / 2048), 256>>>((const uint4*)p_ps, p_ri, (float4*)attn);

    gemm_h<float, false><<<gg, 256, HSMEM_BYTES>>>(p_op, p_wo, b_out, nullptr, out);
}